// round 5
// baseline (speedup 1.0000x reference)
#include <cuda_runtime.h>
#include <cstdint>

// Problem sizes (fixed by the dataset; bounds for static scratch)
static constexpr int NN   = 50000;
static constexpr int EE   = 800000;
static constexpr int BCAP = 64;      // per-node bucket capacity (P(deg>64) ~ 1e-21)

// Scratch (device globals: allocation-free per harness rules)
__device__ __align__(16) float g_x[(long long)NN * 128];  // mlp output [N,128]
__device__ float4 g_h1[NN];              // per-node logits, conv1 (4 heads)
__device__ float4 g_h2[NN];              // per-node logits, conv2 (4 heads)
__device__ int    g_cnt[NN];             // per-src degree (atomic cursor)
__device__ int    g_bkt[(long long)NN * BCAP];  // dst buckets by src

// ---------------------------------------------------------------------------
// Kernel 1: X = feat @ W_mlp + b_mlp  (SGEMM, packed f32x2 FMA — Blackwell FFMA2)
// BM=128, BN=128, BK=16, 256 threads, 8x8 micro-tile per thread
// ---------------------------------------------------------------------------
__global__ __launch_bounds__(256) void gemm_mlp_kernel(
    const float* __restrict__ A,     // feat [N,256]
    const float* __restrict__ B,     // W_mlp [256,128] row-major (K x N)
    const float* __restrict__ bias,  // [128]
    int N)
{
    __shared__ float As[16][128];  // transposed A tile: As[k][m]
    __shared__ float Bs[16][128];  // Bs[k][n]

    const int tid  = threadIdx.x;
    const int brow = blockIdx.x * 128;
    const int tcol = (tid & 15) * 8;   // 0..120
    const int trow = (tid >> 4) * 8;   // 0..120

    unsigned long long acc2[8][4];
#pragma unroll
    for (int i = 0; i < 8; i++)
#pragma unroll
        for (int j = 0; j < 4; j++) acc2[i][j] = 0ull;

    for (int k0 = 0; k0 < 256; k0 += 16) {
#pragma unroll
        for (int i = 0; i < 2; i++) {
            int idx = tid * 2 + i;          // 0..511
            int r   = idx >> 2;             // 0..127
            int c4  = (idx & 3) * 4;        // 0,4,8,12
            int gr  = brow + r;
            float4 v = make_float4(0.f, 0.f, 0.f, 0.f);
            if (gr < N) v = *(const float4*)(A + (long long)gr * 256 + k0 + c4);
            As[c4 + 0][r] = v.x;
            As[c4 + 1][r] = v.y;
            As[c4 + 2][r] = v.z;
            As[c4 + 3][r] = v.w;
        }
#pragma unroll
        for (int i = 0; i < 2; i++) {
            int idx = tid * 2 + i;          // 0..511
            int r   = idx >> 5;             // 0..15
            int c4  = (idx & 31) * 4;       // 0..124
            *(float4*)&Bs[r][c4] = *(const float4*)(B + (long long)(k0 + r) * 128 + c4);
        }
        __syncthreads();

#pragma unroll
        for (int k = 0; k < 16; k++) {
            unsigned long long bn2[4];
            {
                float4 b0 = *(const float4*)&Bs[k][tcol];
                float4 b1 = *(const float4*)&Bs[k][tcol + 4];
                float2 p;
                p = make_float2(b0.x, b0.y); bn2[0] = *reinterpret_cast<unsigned long long*>(&p);
                p = make_float2(b0.z, b0.w); bn2[1] = *reinterpret_cast<unsigned long long*>(&p);
                p = make_float2(b1.x, b1.y); bn2[2] = *reinterpret_cast<unsigned long long*>(&p);
                p = make_float2(b1.z, b1.w); bn2[3] = *reinterpret_cast<unsigned long long*>(&p);
            }
#pragma unroll
            for (int i = 0; i < 8; i++) {
                float a = As[k][trow + i];
                unsigned long long am2;
                asm("mov.b64 %0, {%1, %1};" : "=l"(am2) : "f"(a));
#pragma unroll
                for (int j = 0; j < 4; j++) {
                    asm("fma.rn.f32x2 %0, %1, %2, %3;"
                        : "=l"(acc2[i][j])
                        : "l"(am2), "l"(bn2[j]), "l"(acc2[i][j]));
                }
            }
        }
        __syncthreads();
    }

#pragma unroll
    for (int i = 0; i < 8; i++) {
        int gr = brow + trow + i;
        if (gr < N) {
#pragma unroll
            for (int j = 0; j < 2; j++) {
                float2 p0 = *reinterpret_cast<float2*>(&acc2[i][2 * j + 0]);
                float2 p1 = *reinterpret_cast<float2*>(&acc2[i][2 * j + 1]);
                float4 v;
                v.x = p0.x + bias[tcol + 4 * j + 0];
                v.y = p0.y + bias[tcol + 4 * j + 1];
                v.z = p1.x + bias[tcol + 4 * j + 2];
                v.w = p1.y + bias[tcol + 4 * j + 3];
                *(float4*)(g_x + (long long)gr * 128 + tcol + 4 * j) = v;
            }
        }
    }
}

// ---------------------------------------------------------------------------
// Kernel 2: h1 = feat @ W1^T + b1, h2 = feat @ W2^T + b2   (one warp / node)
// ---------------------------------------------------------------------------
__global__ __launch_bounds__(256) void h_kernel(
    const float* __restrict__ feat,
    const float* __restrict__ W1, const float* __restrict__ b1,
    const float* __restrict__ W2, const float* __restrict__ b2,
    int N)
{
    int warp = (blockIdx.x * blockDim.x + threadIdx.x) >> 5;
    if (warp >= N) return;
    int lane = threadIdx.x & 31;

    float a[4] = {0.f, 0.f, 0.f, 0.f};
    float b[4] = {0.f, 0.f, 0.f, 0.f};
    const float* frow = feat + (long long)warp * 256;
#pragma unroll
    for (int kk = 0; kk < 8; kk++) {
        int k   = lane + kk * 32;
        float f = frow[k];
#pragma unroll
        for (int j = 0; j < 4; j++) {
            a[j] = fmaf(f, __ldg(W1 + j * 256 + k), a[j]);
            b[j] = fmaf(f, __ldg(W2 + j * 256 + k), b[j]);
        }
    }
#pragma unroll
    for (int off = 16; off; off >>= 1) {
#pragma unroll
        for (int j = 0; j < 4; j++) {
            a[j] += __shfl_xor_sync(0xFFFFFFFFu, a[j], off);
            b[j] += __shfl_xor_sync(0xFFFFFFFFu, b[j], off);
        }
    }
    if (lane == 0) {
        g_h1[warp] = make_float4(a[0] + b1[0], a[1] + b1[1], a[2] + b1[2], a[3] + b1[3]);
        g_h2[warp] = make_float4(b[0] + b2[0], b[1] + b2[1], b[2] + b2[2], b[3] + b2[3]);
    }
}

// ---------------------------------------------------------------------------
// Bucket build: zero counts, then single-pass scatter (no scan needed)
// ---------------------------------------------------------------------------
__global__ void zero_cnt_kernel(int N)
{
    int i = blockIdx.x * blockDim.x + threadIdx.x;
    if (i < N) g_cnt[i] = 0;
}

__global__ void scatter_kernel(const int* __restrict__ ei, int E)
{
    int base = (blockIdx.x * blockDim.x + threadIdx.x) * 4;
    if (base >= E) return;

    int s4[4], d4[4];
    if (base + 4 <= E && (E & 3) == 0) {
        int4 sv = *reinterpret_cast<const int4*>(ei + base);
        int4 dv = *reinterpret_cast<const int4*>(ei + E + base);
        s4[0] = sv.x; s4[1] = sv.y; s4[2] = sv.z; s4[3] = sv.w;
        d4[0] = dv.x; d4[1] = dv.y; d4[2] = dv.z; d4[3] = dv.w;
#pragma unroll
        for (int k = 0; k < 4; k++) {
            int pos = atomicAdd(&g_cnt[s4[k]], 1);
            if (pos < BCAP) g_bkt[(long long)s4[k] * BCAP + pos] = d4[k];
        }
    } else {
#pragma unroll
        for (int k = 0; k < 4; k++) {
            int e = base + k;
            if (e < E) {
                int s = __ldg(&ei[e]);
                int d = __ldg(&ei[E + e]);
                int pos = atomicAdd(&g_cnt[s], 1);
                if (pos < BCAP) g_bkt[(long long)s * BCAP + pos] = d;
            }
        }
    }
}

// ---------------------------------------------------------------------------
// Kernel 4: aggregate.  One warp per node, no atomics, 4-deep pipelined.
//   out[n][h*32+f] = sum_{e: src=n} relu(h1[n][h]+h2[dst][h]) * x[dst][h*32+f]
//                    + eps * x[n][h*32+f]
// ---------------------------------------------------------------------------
__global__ __launch_bounds__(256) void agg_kernel(
    const float* __restrict__ eps,
    float* __restrict__ OUT,
    int N)
{
    int node = (blockIdx.x * blockDim.x + threadIdx.x) >> 5;
    if (node >= N) return;
    int lane = threadIdx.x & 31;
    int head = lane >> 3;           // 4 heads, 8 lanes each
    int j    = lane * 4;            // feature offset (float4)

    float4 ha = g_h1[node];
    float ha_h = (head == 0) ? ha.x : (head == 1) ? ha.y
               : (head == 2) ? ha.z : ha.w;

    int cnt = g_cnt[node];
    if (cnt > BCAP) cnt = BCAP;
    const int* bkt = g_bkt + (long long)node * BCAP;

    float4 acc[4];
#pragma unroll
    for (int k = 0; k < 4; k++) acc[k] = make_float4(0.f, 0.f, 0.f, 0.f);

    // Pipeline: prefetch batch of 4 (dst, v); overlap next-batch prefetch
    // with current batch's x gathers + fma.
    int   dc[4];
    float vc[4];
#pragma unroll
    for (int k = 0; k < 4; k++) {
        if (k < cnt) {
            int d = __ldg(&bkt[k]);
            dc[k] = d;
            float4 hb = g_h2[d];
            float hbh = (head == 0) ? hb.x : (head == 1) ? hb.y
                      : (head == 2) ? hb.z : hb.w;
            vc[k] = ha_h + hbh;
        } else { dc[k] = 0; vc[k] = -1.f; }
    }

    for (int i = 0; i < cnt; i += 4) {
        int   dn[4];
        float vn[4];
#pragma unroll
        for (int k = 0; k < 4; k++) {
            int idx = i + 4 + k;
            if (idx < cnt) {
                int d = __ldg(&bkt[idx]);
                dn[k] = d;
                float4 hb = g_h2[d];
                float hbh = (head == 0) ? hb.x : (head == 1) ? hb.y
                          : (head == 2) ? hb.z : hb.w;
                vn[k] = ha_h + hbh;
            } else { dn[k] = 0; vn[k] = -1.f; }
        }
#pragma unroll
        for (int k = 0; k < 4; k++) {
            if (vc[k] > 0.f) {  // relu zero-skip: drop the gather entirely
                float4 xv = *(const float4*)(g_x + (long long)dc[k] * 128 + j);
                acc[k].x = fmaf(vc[k], xv.x, acc[k].x);
                acc[k].y = fmaf(vc[k], xv.y, acc[k].y);
                acc[k].z = fmaf(vc[k], xv.z, acc[k].z);
                acc[k].w = fmaf(vc[k], xv.w, acc[k].w);
            }
        }
#pragma unroll
        for (int k = 0; k < 4; k++) { dc[k] = dn[k]; vc[k] = vn[k]; }
    }

    float e0 = eps[0];
    float4 xs = *(const float4*)(g_x + (long long)node * 128 + j);
    float4 o;
    o.x = fmaf(e0, xs.x, (acc[0].x + acc[1].x) + (acc[2].x + acc[3].x));
    o.y = fmaf(e0, xs.y, (acc[0].y + acc[1].y) + (acc[2].y + acc[3].y));
    o.z = fmaf(e0, xs.z, (acc[0].z + acc[1].z) + (acc[2].z + acc[3].z));
    o.w = fmaf(e0, xs.w, (acc[0].w + acc[1].w) + (acc[2].w + acc[3].w));
    *(float4*)(OUT + (long long)node * 128 + j) = o;
}

// ---------------------------------------------------------------------------
extern "C" void kernel_launch(void* const* d_in, const int* in_sizes, int n_in,
                              void* d_out, int out_size)
{
    const float* feat  = (const float*)d_in[0];
    const int*   ei    = (const int*)d_in[1];
    const float* W_mlp = (const float*)d_in[2];
    const float* b_mlp = (const float*)d_in[3];
    const float* W1    = (const float*)d_in[4];
    const float* b1    = (const float*)d_in[5];
    const float* W2    = (const float*)d_in[6];
    const float* b2    = (const float*)d_in[7];
    const float* eps   = (const float*)d_in[8];

    const int N = in_sizes[0] / 256;
    const int E = in_sizes[1] / 2;
    float* out = (float*)d_out;

    // One-time side stream + fork/join events (host objects, no device mem)
    static cudaStream_t s_side = nullptr;
    static cudaEvent_t  ev_fork = nullptr, ev_join = nullptr;
    if (!s_side) {
        cudaStreamCreateWithFlags(&s_side, cudaStreamNonBlocking);
        cudaEventCreateWithFlags(&ev_fork, cudaEventDisableTiming);
        cudaEventCreateWithFlags(&ev_join, cudaEventDisableTiming);
    }

    // Fork: bucket build + h projections on side stream, under the GEMM.
    cudaEventRecord(ev_fork, 0);
    cudaStreamWaitEvent(s_side, ev_fork, 0);

    zero_cnt_kernel<<<(N + 511) / 512, 512, 0, s_side>>>(N);
    scatter_kernel<<<(E / 4 + 255) / 256, 256, 0, s_side>>>(ei, E);
    h_kernel<<<(N + 7) / 8, 256, 0, s_side>>>(feat, W1, b1, W2, b2, N);
    cudaEventRecord(ev_join, s_side);

    // Dense chain on capture (NULL) stream.
    gemm_mlp_kernel<<<(N + 127) / 128, 256>>>(feat, W_mlp, b_mlp, N);

    // Join, then atomic-free aggregation + epilogue.
    cudaStreamWaitEvent(0, ev_join, 0);
    agg_kernel<<<(N + 7) / 8, 256>>>(eps, out, N);
}

// round 6
// speedup vs baseline: 1.1298x; 1.1298x over previous
#include <cuda_runtime.h>
#include <cstdint>

// Problem sizes (fixed by the dataset; bounds for static scratch)
static constexpr int NN = 50000;
static constexpr int EE = 800000;

// Scratch (device globals: allocation-free per harness rules)
__device__ __align__(16) float g_x[(long long)NN * 128];  // mlp output [N,128]
__device__ float4 g_h1[NN];        // per-node logits, conv1 (4 heads)
__device__ float4 g_h2[NN];        // per-node logits, conv2 (4 heads)
__device__ int    g_cnt[NN];       // per-src degree
__device__ int    g_off[NN + 1];   // CSR row offsets
__device__ int    g_cur[NN];       // scatter cursors
__device__ int    g_sdst[EE];      // dst sorted by src

// ---------------------------------------------------------------------------
// Kernel 1: X = feat @ W_mlp + b_mlp  (SGEMM, packed f32x2 FMA — Blackwell FFMA2)
// BM=128, BN=128, BK=16, 256 threads, 8x8 micro-tile per thread.
// Both A and B fragments read via LDS.128 (vectorized).
// ---------------------------------------------------------------------------
__global__ __launch_bounds__(256) void gemm_mlp_kernel(
    const float* __restrict__ A,     // feat [N,256]
    const float* __restrict__ B,     // W_mlp [256,128] row-major (K x N)
    const float* __restrict__ bias,  // [128]
    int N)
{
    __shared__ float As[16][128];  // transposed A tile: As[k][m]
    __shared__ float Bs[16][128];  // Bs[k][n]

    const int tid  = threadIdx.x;
    const int brow = blockIdx.x * 128;
    const int tcol = (tid & 15) * 8;   // 0..120
    const int trow = (tid >> 4) * 8;   // 0..120

    unsigned long long acc2[8][4];
#pragma unroll
    for (int i = 0; i < 8; i++)
#pragma unroll
        for (int j = 0; j < 4; j++) acc2[i][j] = 0ull;

    for (int k0 = 0; k0 < 256; k0 += 16) {
#pragma unroll
        for (int i = 0; i < 2; i++) {
            int idx = tid * 2 + i;          // 0..511
            int r   = idx >> 2;             // 0..127
            int c4  = (idx & 3) * 4;        // 0,4,8,12
            int gr  = brow + r;
            float4 v = make_float4(0.f, 0.f, 0.f, 0.f);
            if (gr < N) v = *(const float4*)(A + (long long)gr * 256 + k0 + c4);
            As[c4 + 0][r] = v.x;
            As[c4 + 1][r] = v.y;
            As[c4 + 2][r] = v.z;
            As[c4 + 3][r] = v.w;
        }
#pragma unroll
        for (int i = 0; i < 2; i++) {
            int idx = tid * 2 + i;          // 0..511
            int r   = idx >> 5;             // 0..15
            int c4  = (idx & 31) * 4;       // 0..124
            *(float4*)&Bs[r][c4] = *(const float4*)(B + (long long)(k0 + r) * 128 + c4);
        }
        __syncthreads();

#pragma unroll
        for (int k = 0; k < 16; k++) {
            // B fragment: 2 x LDS.128
            unsigned long long bn2[4];
            {
                float4 b0 = *(const float4*)&Bs[k][tcol];
                float4 b1 = *(const float4*)&Bs[k][tcol + 4];
                float2 p;
                p = make_float2(b0.x, b0.y); bn2[0] = *reinterpret_cast<unsigned long long*>(&p);
                p = make_float2(b0.z, b0.w); bn2[1] = *reinterpret_cast<unsigned long long*>(&p);
                p = make_float2(b1.x, b1.y); bn2[2] = *reinterpret_cast<unsigned long long*>(&p);
                p = make_float2(b1.z, b1.w); bn2[3] = *reinterpret_cast<unsigned long long*>(&p);
            }
            // A fragment: 2 x LDS.128 (was 8 scalar LDS.32)
            float am[8];
            {
                float4 a0 = *(const float4*)&As[k][trow];
                float4 a1 = *(const float4*)&As[k][trow + 4];
                am[0] = a0.x; am[1] = a0.y; am[2] = a0.z; am[3] = a0.w;
                am[4] = a1.x; am[5] = a1.y; am[6] = a1.z; am[7] = a1.w;
            }
#pragma unroll
            for (int i = 0; i < 8; i++) {
                unsigned long long am2;
                asm("mov.b64 %0, {%1, %1};" : "=l"(am2) : "f"(am[i]));
#pragma unroll
                for (int j = 0; j < 4; j++) {
                    asm("fma.rn.f32x2 %0, %1, %2, %3;"
                        : "=l"(acc2[i][j])
                        : "l"(am2), "l"(bn2[j]), "l"(acc2[i][j]));
                }
            }
        }
        __syncthreads();
    }

#pragma unroll
    for (int i = 0; i < 8; i++) {
        int gr = brow + trow + i;
        if (gr < N) {
#pragma unroll
            for (int j = 0; j < 2; j++) {
                float2 p0 = *reinterpret_cast<float2*>(&acc2[i][2 * j + 0]);
                float2 p1 = *reinterpret_cast<float2*>(&acc2[i][2 * j + 1]);
                float4 v;
                v.x = p0.x + bias[tcol + 4 * j + 0];
                v.y = p0.y + bias[tcol + 4 * j + 1];
                v.z = p1.x + bias[tcol + 4 * j + 2];
                v.w = p1.y + bias[tcol + 4 * j + 3];
                *(float4*)(g_x + (long long)gr * 128 + tcol + 4 * j) = v;
            }
        }
    }
}

// ---------------------------------------------------------------------------
// Kernel 2: h1 = feat @ W1^T + b1, h2 = feat @ W2^T + b2   (one warp / node)
// ---------------------------------------------------------------------------
__global__ __launch_bounds__(256) void h_kernel(
    const float* __restrict__ feat,
    const float* __restrict__ W1, const float* __restrict__ b1,
    const float* __restrict__ W2, const float* __restrict__ b2,
    int N)
{
    int warp = (blockIdx.x * blockDim.x + threadIdx.x) >> 5;
    if (warp >= N) return;
    int lane = threadIdx.x & 31;

    float a[4] = {0.f, 0.f, 0.f, 0.f};
    float b[4] = {0.f, 0.f, 0.f, 0.f};
    const float* frow = feat + (long long)warp * 256;
#pragma unroll
    for (int kk = 0; kk < 8; kk++) {
        int k   = lane + kk * 32;
        float f = frow[k];
#pragma unroll
        for (int j = 0; j < 4; j++) {
            a[j] = fmaf(f, __ldg(W1 + j * 256 + k), a[j]);
            b[j] = fmaf(f, __ldg(W2 + j * 256 + k), b[j]);
        }
    }
#pragma unroll
    for (int off = 16; off; off >>= 1) {
#pragma unroll
        for (int j = 0; j < 4; j++) {
            a[j] += __shfl_xor_sync(0xFFFFFFFFu, a[j], off);
            b[j] += __shfl_xor_sync(0xFFFFFFFFu, b[j], off);
        }
    }
    if (lane == 0) {
        g_h1[warp] = make_float4(a[0] + b1[0], a[1] + b1[1], a[2] + b1[2], a[3] + b1[3]);
        g_h2[warp] = make_float4(b[0] + b2[0], b[1] + b2[1], b[2] + b2[2], b[3] + b2[3]);
    }
}

// ---------------------------------------------------------------------------
// CSR build: zero counts, count degrees, scan, scatter dst by src
// ---------------------------------------------------------------------------
__global__ void zero_cnt_kernel(int N)
{
    int i = blockIdx.x * blockDim.x + threadIdx.x;
    if (i < N) g_cnt[i] = 0;
}

__global__ void count_kernel(const int* __restrict__ ei, int E)
{
    int e = blockIdx.x * blockDim.x + threadIdx.x;
    if (e < E) atomicAdd(&g_cnt[ei[e]], 1);
}

__global__ __launch_bounds__(1024) void scan_kernel(int N)
{
    __shared__ int warp_sums[32];
    __shared__ int s_carry;
    const int tid = threadIdx.x, lane = tid & 31, wid = tid >> 5;
    if (tid == 0) s_carry = 0;
    __syncthreads();

    for (int base = 0; base < N; base += 1024) {
        int i = base + tid;
        int v = (i < N) ? g_cnt[i] : 0;
        int x = v;
#pragma unroll
        for (int o = 1; o < 32; o <<= 1) {
            int y = __shfl_up_sync(0xFFFFFFFFu, x, o);
            if (lane >= o) x += y;
        }
        if (lane == 31) warp_sums[wid] = x;
        __syncthreads();
        if (wid == 0) {
            int s = warp_sums[lane];
#pragma unroll
            for (int o = 1; o < 32; o <<= 1) {
                int y = __shfl_up_sync(0xFFFFFFFFu, s, o);
                if (lane >= o) s += y;
            }
            warp_sums[lane] = s;
        }
        __syncthreads();
        int warp_off = (wid == 0) ? 0 : warp_sums[wid - 1];
        int excl = s_carry + warp_off + x - v;
        if (i < N) { g_off[i] = excl; g_cur[i] = excl; }
        int chunk_total = warp_sums[31];
        __syncthreads();
        if (tid == 0) s_carry += chunk_total;
        __syncthreads();
    }
    if (tid == 0) g_off[N] = s_carry;
}

__global__ void scatter_kernel(const int* __restrict__ ei, int E)
{
    int e = blockIdx.x * blockDim.x + threadIdx.x;
    if (e < E) {
        int s = ei[e];
        int d = ei[E + e];
        int pos = atomicAdd(&g_cur[s], 1);
        g_sdst[pos] = d;
    }
}

// ---------------------------------------------------------------------------
// Kernel 4: aggregate.  One warp per node, no atomics, 2-edge ILP.
//   out[n][h*32+f] = sum_{e: src=n} relu(h1[n][h]+h2[dst][h]) * x[dst][h*32+f]
//                    + eps * x[n][h*32+f]
// ---------------------------------------------------------------------------
__global__ __launch_bounds__(256) void agg_kernel(
    const float* __restrict__ eps,
    float* __restrict__ OUT,
    int N)
{
    int node = (blockIdx.x * blockDim.x + threadIdx.x) >> 5;
    if (node >= N) return;
    int lane = threadIdx.x & 31;
    int head = lane >> 3;           // 4 heads, 8 lanes each
    int j    = lane * 4;            // feature offset (float4)

    float4 ha = g_h1[node];
    float ha_h = (head < 2) ? (head == 0 ? ha.x : ha.y)
                            : (head == 2 ? ha.z : ha.w);

    int i   = g_off[node];
    int end = g_off[node + 1];

    float4 acc0 = make_float4(0.f, 0.f, 0.f, 0.f);
    float4 acc1 = make_float4(0.f, 0.f, 0.f, 0.f);

    for (; i + 2 <= end; i += 2) {
        int d0 = __ldg(&g_sdst[i]);
        int d1 = __ldg(&g_sdst[i + 1]);
        float4 hb0 = g_h2[d0];
        float4 hb1 = g_h2[d1];
        float v0 = ha_h + ((head < 2) ? (head == 0 ? hb0.x : hb0.y)
                                      : (head == 2 ? hb0.z : hb0.w));
        float v1 = ha_h + ((head < 2) ? (head == 0 ? hb1.x : hb1.y)
                                      : (head == 2 ? hb1.z : hb1.w));
        if (v0 > 0.f) {
            float4 xv = *(const float4*)(g_x + (long long)d0 * 128 + j);
            acc0.x = fmaf(v0, xv.x, acc0.x);
            acc0.y = fmaf(v0, xv.y, acc0.y);
            acc0.z = fmaf(v0, xv.z, acc0.z);
            acc0.w = fmaf(v0, xv.w, acc0.w);
        }
        if (v1 > 0.f) {
            float4 xv = *(const float4*)(g_x + (long long)d1 * 128 + j);
            acc1.x = fmaf(v1, xv.x, acc1.x);
            acc1.y = fmaf(v1, xv.y, acc1.y);
            acc1.z = fmaf(v1, xv.z, acc1.z);
            acc1.w = fmaf(v1, xv.w, acc1.w);
        }
    }
    if (i < end) {  // tail edge
        int d0 = __ldg(&g_sdst[i]);
        float4 hb0 = g_h2[d0];
        float v0 = ha_h + ((head < 2) ? (head == 0 ? hb0.x : hb0.y)
                                      : (head == 2 ? hb0.z : hb0.w));
        if (v0 > 0.f) {
            float4 xv = *(const float4*)(g_x + (long long)d0 * 128 + j);
            acc0.x = fmaf(v0, xv.x, acc0.x);
            acc0.y = fmaf(v0, xv.y, acc0.y);
            acc0.z = fmaf(v0, xv.z, acc0.z);
            acc0.w = fmaf(v0, xv.w, acc0.w);
        }
    }

    float e0 = eps[0];
    float4 xs = *(const float4*)(g_x + (long long)node * 128 + j);
    float4 o;
    o.x = fmaf(e0, xs.x, acc0.x + acc1.x);
    o.y = fmaf(e0, xs.y, acc0.y + acc1.y);
    o.z = fmaf(e0, xs.z, acc0.z + acc1.z);
    o.w = fmaf(e0, xs.w, acc0.w + acc1.w);
    *(float4*)(OUT + (long long)node * 128 + j) = o;
}

// ---------------------------------------------------------------------------
extern "C" void kernel_launch(void* const* d_in, const int* in_sizes, int n_in,
                              void* d_out, int out_size)
{
    const float* feat  = (const float*)d_in[0];
    const int*   ei    = (const int*)d_in[1];
    const float* W_mlp = (const float*)d_in[2];
    const float* b_mlp = (const float*)d_in[3];
    const float* W1    = (const float*)d_in[4];
    const float* b1    = (const float*)d_in[5];
    const float* W2    = (const float*)d_in[6];
    const float* b2    = (const float*)d_in[7];
    const float* eps   = (const float*)d_in[8];

    const int N = in_sizes[0] / 256;
    const int E = in_sizes[1] / 2;
    float* out = (float*)d_out;

    // One-time side stream + fork/join events (host objects, no device mem)
    static cudaStream_t s_side = nullptr;
    static cudaEvent_t  ev_fork = nullptr, ev_join = nullptr;
    if (!s_side) {
        cudaStreamCreateWithFlags(&s_side, cudaStreamNonBlocking);
        cudaEventCreateWithFlags(&ev_fork, cudaEventDisableTiming);
        cudaEventCreateWithFlags(&ev_join, cudaEventDisableTiming);
    }

    // Fork: CSR build + h projections on side stream, under the GEMM.
    cudaEventRecord(ev_fork, 0);
    cudaStreamWaitEvent(s_side, ev_fork, 0);

    zero_cnt_kernel<<<(N + 511) / 512, 512, 0, s_side>>>(N);
    count_kernel<<<(E + 255) / 256, 256, 0, s_side>>>(ei, E);
    scan_kernel<<<1, 1024, 0, s_side>>>(N);
    scatter_kernel<<<(E + 255) / 256, 256, 0, s_side>>>(ei, E);
    h_kernel<<<(N + 7) / 8, 256, 0, s_side>>>(feat, W1, b1, W2, b2, N);
    cudaEventRecord(ev_join, s_side);

    // Dense chain on capture (NULL) stream.
    gemm_mlp_kernel<<<(N + 127) / 128, 256>>>(feat, W_mlp, b_mlp, N);

    // Join, then atomic-free aggregation + epilogue.
    cudaStreamWaitEvent(0, ev_join, 0);
    agg_kernel<<<(N + 7) / 8, 256>>>(eps, out, N);
}

// round 8
// speedup vs baseline: 1.1369x; 1.0063x over previous
#include <cuda_runtime.h>
#include <cstdint>

// Problem sizes (fixed by the dataset; bounds for static scratch)
static constexpr int NN = 50000;
static constexpr int EE = 800000;

// Scratch (device globals: allocation-free per harness rules)
__device__ __align__(16) float g_x[(long long)NN * 128];  // mlp output [N,128]
__device__ float4 g_h1[NN];        // per-node logits, conv1 (4 heads)
__device__ float4 g_h2[NN];        // per-node logits, conv2 (4 heads)
__device__ int    g_cnt[NN];       // per-src degree
__device__ int    g_off[NN + 1];   // CSR row offsets
__device__ int    g_cur[NN];       // scatter cursors
__device__ int    g_sdst[EE];      // dst sorted by src

// ---------------------------------------------------------------------------
// Half-GEMM: g_x[:, colofs..colofs+63] = feat @ W_mlp[:, colofs..+63] + bias
// BM=128, BN=64, BK=16, 256 threads, 8x4 micro-tile, packed f32x2 FMA.
// ---------------------------------------------------------------------------
__global__ __launch_bounds__(256) void gemm_half_kernel(
    const float* __restrict__ A,     // feat [N,256]
    const float* __restrict__ B,     // W_mlp [256,128] row-major (K x N)
    const float* __restrict__ bias,  // [128]
    int N, int colofs)
{
    __shared__ float As[16][128];  // transposed A tile: As[k][m]
    __shared__ float Bs[16][64];   // Bs[k][n]

    const int tid  = threadIdx.x;
    const int brow = blockIdx.x * 128;
    const int tcol = (tid & 15) * 4;   // 0..60
    const int trow = (tid >> 4) * 8;   // 0..120

    unsigned long long acc2[8][2];
#pragma unroll
    for (int i = 0; i < 8; i++) { acc2[i][0] = 0ull; acc2[i][1] = 0ull; }

    for (int k0 = 0; k0 < 256; k0 += 16) {
        // A tile: 128 rows x 16 k, transposed.  2 float4 / thread.
#pragma unroll
        for (int i = 0; i < 2; i++) {
            int idx = tid * 2 + i;          // 0..511
            int r   = idx >> 2;             // 0..127
            int c4  = (idx & 3) * 4;        // 0,4,8,12
            int gr  = brow + r;
            float4 v = make_float4(0.f, 0.f, 0.f, 0.f);
            if (gr < N) v = *(const float4*)(A + (long long)gr * 256 + k0 + c4);
            As[c4 + 0][r] = v.x;
            As[c4 + 1][r] = v.y;
            As[c4 + 2][r] = v.z;
            As[c4 + 3][r] = v.w;
        }
        // B tile: 16 k x 64 n.  1 float4 / thread.
        {
            int r  = tid >> 4;              // 0..15
            int c4 = (tid & 15) * 4;        // 0..60
            *(float4*)&Bs[r][c4] =
                *(const float4*)(B + (long long)(k0 + r) * 128 + colofs + c4);
        }
        __syncthreads();

#pragma unroll
        for (int k = 0; k < 16; k++) {
            unsigned long long bn2[2];
            {
                float4 b0 = *(const float4*)&Bs[k][tcol];
                float2 p;
                p = make_float2(b0.x, b0.y); bn2[0] = *reinterpret_cast<unsigned long long*>(&p);
                p = make_float2(b0.z, b0.w); bn2[1] = *reinterpret_cast<unsigned long long*>(&p);
            }
            float am[8];
            {
                float4 a0 = *(const float4*)&As[k][trow];
                float4 a1 = *(const float4*)&As[k][trow + 4];
                am[0] = a0.x; am[1] = a0.y; am[2] = a0.z; am[3] = a0.w;
                am[4] = a1.x; am[5] = a1.y; am[6] = a1.z; am[7] = a1.w;
            }
#pragma unroll
            for (int i = 0; i < 8; i++) {
                unsigned long long am2;
                asm("mov.b64 %0, {%1, %1};" : "=l"(am2) : "f"(am[i]));
                asm("fma.rn.f32x2 %0, %1, %2, %3;"
                    : "=l"(acc2[i][0]) : "l"(am2), "l"(bn2[0]), "l"(acc2[i][0]));
                asm("fma.rn.f32x2 %0, %1, %2, %3;"
                    : "=l"(acc2[i][1]) : "l"(am2), "l"(bn2[1]), "l"(acc2[i][1]));
            }
        }
        __syncthreads();
    }

#pragma unroll
    for (int i = 0; i < 8; i++) {
        int gr = brow + trow + i;
        if (gr < N) {
            float2 p0 = *reinterpret_cast<float2*>(&acc2[i][0]);
            float2 p1 = *reinterpret_cast<float2*>(&acc2[i][1]);
            float4 v;
            v.x = p0.x + __ldg(bias + colofs + tcol + 0);
            v.y = p0.y + __ldg(bias + colofs + tcol + 1);
            v.z = p1.x + __ldg(bias + colofs + tcol + 2);
            v.w = p1.y + __ldg(bias + colofs + tcol + 3);
            *(float4*)(g_x + (long long)gr * 128 + colofs + tcol) = v;
        }
    }
}

// ---------------------------------------------------------------------------
// Kernel 2: h1 = feat @ W1^T + b1, h2 = feat @ W2^T + b2   (one warp / node)
// ---------------------------------------------------------------------------
__global__ __launch_bounds__(256) void h_kernel(
    const float* __restrict__ feat,
    const float* __restrict__ W1, const float* __restrict__ b1,
    const float* __restrict__ W2, const float* __restrict__ b2,
    int N)
{
    int warp = (blockIdx.x * blockDim.x + threadIdx.x) >> 5;
    if (warp >= N) return;
    int lane = threadIdx.x & 31;

    float a[4] = {0.f, 0.f, 0.f, 0.f};
    float b[4] = {0.f, 0.f, 0.f, 0.f};
    const float* frow = feat + (long long)warp * 256;
#pragma unroll
    for (int kk = 0; kk < 8; kk++) {
        int k   = lane + kk * 32;
        float f = frow[k];
#pragma unroll
        for (int j = 0; j < 4; j++) {
            a[j] = fmaf(f, __ldg(W1 + j * 256 + k), a[j]);
            b[j] = fmaf(f, __ldg(W2 + j * 256 + k), b[j]);
        }
    }
#pragma unroll
    for (int off = 16; off; off >>= 1) {
#pragma unroll
        for (int j = 0; j < 4; j++) {
            a[j] += __shfl_xor_sync(0xFFFFFFFFu, a[j], off);
            b[j] += __shfl_xor_sync(0xFFFFFFFFu, b[j], off);
        }
    }
    if (lane == 0) {
        g_h1[warp] = make_float4(a[0] + b1[0], a[1] + b1[1], a[2] + b1[2], a[3] + b1[3]);
        g_h2[warp] = make_float4(b[0] + b2[0], b[1] + b2[1], b[2] + b2[2], b[3] + b2[3]);
    }
}

// ---------------------------------------------------------------------------
// CSR build: zero counts, count degrees, scan, scatter dst by src
// ---------------------------------------------------------------------------
__global__ void zero_cnt_kernel(int N)
{
    int i = blockIdx.x * blockDim.x + threadIdx.x;
    if (i < N) g_cnt[i] = 0;
}

__global__ void count_kernel(const int* __restrict__ ei, int E)
{
    int e = blockIdx.x * blockDim.x + threadIdx.x;
    if (e < E) atomicAdd(&g_cnt[ei[e]], 1);
}

__global__ __launch_bounds__(1024) void scan_kernel(int N)
{
    __shared__ int warp_sums[32];
    __shared__ int s_carry;
    const int tid = threadIdx.x, lane = tid & 31, wid = tid >> 5;
    if (tid == 0) s_carry = 0;
    __syncthreads();

    for (int base = 0; base < N; base += 1024) {
        int i = base + tid;
        int v = (i < N) ? g_cnt[i] : 0;
        int x = v;
#pragma unroll
        for (int o = 1; o < 32; o <<= 1) {
            int y = __shfl_up_sync(0xFFFFFFFFu, x, o);
            if (lane >= o) x += y;
        }
        if (lane == 31) warp_sums[wid] = x;
        __syncthreads();
        if (wid == 0) {
            int s = warp_sums[lane];
#pragma unroll
            for (int o = 1; o < 32; o <<= 1) {
                int y = __shfl_up_sync(0xFFFFFFFFu, s, o);
                if (lane >= o) s += y;
            }
            warp_sums[lane] = s;
        }
        __syncthreads();
        int warp_off = (wid == 0) ? 0 : warp_sums[wid - 1];
        int excl = s_carry + warp_off + x - v;
        if (i < N) { g_off[i] = excl; g_cur[i] = excl; }
        int chunk_total = warp_sums[31];
        __syncthreads();
        if (tid == 0) s_carry += chunk_total;
        __syncthreads();
    }
    if (tid == 0) g_off[N] = s_carry;
}

__global__ void scatter_kernel(const int* __restrict__ ei, int E)
{
    int e = blockIdx.x * blockDim.x + threadIdx.x;
    if (e < E) {
        int s = ei[e];
        int d = ei[E + e];
        int pos = atomicAdd(&g_cur[s], 1);
        g_sdst[pos] = d;
    }
}

// ---------------------------------------------------------------------------
// Half-aggregate: columns [colofs, colofs+64).  One warp per node, float2/lane.
//   out[n][j] = sum_{e: src=n} relu(h1[n][h]+h2[dst][h]) * x[dst][j]
//               + eps * x[n][j],   j = colofs + lane*2, h = j/32
// ---------------------------------------------------------------------------
__device__ __forceinline__ float head_sel(const float4 h, int head) {
    return (head & 2) ? ((head & 1) ? h.w : h.z)
                      : ((head & 1) ? h.y : h.x);
}

__global__ __launch_bounds__(256) void agg_half_kernel(
    const float* __restrict__ eps,
    float* __restrict__ OUT,
    int N, int colofs)
{
    int node = (blockIdx.x * blockDim.x + threadIdx.x) >> 5;
    if (node >= N) return;
    int lane = threadIdx.x & 31;
    int j    = colofs + lane * 2;   // feature offset (float2)
    int head = j >> 5;

    float ha_h = head_sel(g_h1[node], head);

    int i   = g_off[node];
    int end = g_off[node + 1];

    float2 acc0 = make_float2(0.f, 0.f);
    float2 acc1 = make_float2(0.f, 0.f);

    for (; i + 2 <= end; i += 2) {
        int d0 = __ldg(&g_sdst[i]);
        int d1 = __ldg(&g_sdst[i + 1]);
        float v0 = ha_h + head_sel(g_h2[d0], head);
        float v1 = ha_h + head_sel(g_h2[d1], head);
        if (v0 > 0.f) {
            float2 xv = *(const float2*)(g_x + (long long)d0 * 128 + j);
            acc0.x = fmaf(v0, xv.x, acc0.x);
            acc0.y = fmaf(v0, xv.y, acc0.y);
        }
        if (v1 > 0.f) {
            float2 xv = *(const float2*)(g_x + (long long)d1 * 128 + j);
            acc1.x = fmaf(v1, xv.x, acc1.x);
            acc1.y = fmaf(v1, xv.y, acc1.y);
        }
    }
    if (i < end) {  // tail edge
        int d0 = __ldg(&g_sdst[i]);
        float v0 = ha_h + head_sel(g_h2[d0], head);
        if (v0 > 0.f) {
            float2 xv = *(const float2*)(g_x + (long long)d0 * 128 + j);
            acc0.x = fmaf(v0, xv.x, acc0.x);
            acc0.y = fmaf(v0, xv.y, acc0.y);
        }
    }

    float e0 = eps[0];
    float2 xs = *(const float2*)(g_x + (long long)node * 128 + j);
    float2 o;
    o.x = fmaf(e0, xs.x, acc0.x + acc1.x);
    o.y = fmaf(e0, xs.y, acc0.y + acc1.y);
    *(float2*)(OUT + (long long)node * 128 + j) = o;
}

// ---------------------------------------------------------------------------
extern "C" void kernel_launch(void* const* d_in, const int* in_sizes, int n_in,
                              void* d_out, int out_size)
{
    const float* feat  = (const float*)d_in[0];
    const int*   ei    = (const int*)d_in[1];
    const float* W_mlp = (const float*)d_in[2];
    const float* b_mlp = (const float*)d_in[3];
    const float* W1    = (const float*)d_in[4];
    const float* b1    = (const float*)d_in[5];
    const float* W2    = (const float*)d_in[6];
    const float* b2    = (const float*)d_in[7];
    const float* eps   = (const float*)d_in[8];

    const int N = in_sizes[0] / 256;
    const int E = in_sizes[1] / 2;
    float* out = (float*)d_out;

    // One-time streams + events (host objects, no device mem)
    static cudaStream_t s_side = nullptr, s_agg = nullptr;
    static cudaEvent_t  ev_fork = nullptr, ev_join = nullptr,
                        ev_g0 = nullptr, ev_a0 = nullptr;
    if (!s_side) {
        cudaStreamCreateWithFlags(&s_side, cudaStreamNonBlocking);
        cudaStreamCreateWithFlags(&s_agg,  cudaStreamNonBlocking);
        cudaEventCreateWithFlags(&ev_fork, cudaEventDisableTiming);
        cudaEventCreateWithFlags(&ev_join, cudaEventDisableTiming);
        cudaEventCreateWithFlags(&ev_g0,   cudaEventDisableTiming);
        cudaEventCreateWithFlags(&ev_a0,   cudaEventDisableTiming);
    }

    // Fork: CSR build + h projections on side stream.
    cudaEventRecord(ev_fork, 0);
    cudaStreamWaitEvent(s_side, ev_fork, 0);
    cudaStreamWaitEvent(s_agg,  ev_fork, 0);

    zero_cnt_kernel<<<(N + 511) / 512, 512, 0, s_side>>>(N);
    count_kernel<<<(E + 255) / 256, 256, 0, s_side>>>(ei, E);
    scan_kernel<<<1, 1024, 0, s_side>>>(N);
    scatter_kernel<<<(E + 255) / 256, 256, 0, s_side>>>(ei, E);
    h_kernel<<<(N + 7) / 8, 256, 0, s_side>>>(feat, W1, b1, W2, b2, N);
    cudaEventRecord(ev_join, s_side);

    // Main stream: half-GEMM 0 (cols 0-63), then half-GEMM 1 (cols 64-127).
    gemm_half_kernel<<<(N + 127) / 128, 256>>>(feat, W_mlp, b_mlp, N, 0);
    cudaEventRecord(ev_g0, 0);
    gemm_half_kernel<<<(N + 127) / 128, 256>>>(feat, W_mlp, b_mlp, N, 64);

    // Agg half 0 on s_agg: overlaps with half-GEMM 1.
    cudaStreamWaitEvent(s_agg, ev_g0, 0);
    cudaStreamWaitEvent(s_agg, ev_join, 0);
    agg_half_kernel<<<(N + 7) / 8, 256, 0, s_agg>>>(eps, out, N, 0);
    cudaEventRecord(ev_a0, s_agg);

    // Agg half 1 on main after half-GEMM 1 + CSR join; then join agg half 0.
    cudaStreamWaitEvent(0, ev_join, 0);
    agg_half_kernel<<<(N + 7) / 8, 256>>>(eps, out, N, 64);
    cudaStreamWaitEvent(0, ev_a0, 0);
}